// round 8
// baseline (speedup 1.0000x reference)
#include <cuda_runtime.h>
#include <cuda_bf16.h>
#include <math.h>

// Problem constants
#define B_   4
#define C_   128
#define H_   64
#define W_   64
#define OUT_ 128
#define LK   25

typedef unsigned int uint;

// ---------------------------------------------------------------------------
// Device scratch: bf16-split MMA A-fragments
// ---------------------------------------------------------------------------
__device__ uint4 g_w1f[288 * 32];   // conv: F=(((c32*9+tap)*2+ks16)*2+mt)*2+split
__device__ uint4 g_w2f[128 * 32];   // z:    F=(mt*8+ks)*2+split

__device__ __forceinline__ uint cvt2(float hi_src, float lo_src) {
    uint r;
    asm("cvt.rn.bf16x2.f32 %0, %1, %2;" : "=r"(r) : "f"(hi_src), "f"(lo_src));
    return r;
}
__device__ __forceinline__ float uaf(uint u) { return __uint_as_float(u); }

__device__ __forceinline__ void split2(float f0, float f1, uint& hw, uint& lw) {
    hw = cvt2(f1, f0);
    float h0 = uaf(hw << 16);
    float h1 = uaf(hw & 0xFFFF0000u);
    lw = cvt2(f1 - h1, f0 - h0);
}

__device__ __forceinline__ void mma4(float* d, uint4 A, uint b0, uint b1) {
    asm("mma.sync.aligned.m16n8k16.row.col.f32.bf16.bf16.f32 "
        "{%0,%1,%2,%3}, {%4,%5,%6,%7}, {%8,%9}, {%0,%1,%2,%3};"
        : "+f"(d[0]), "+f"(d[1]), "+f"(d[2]), "+f"(d[3])
        : "r"(A.x), "r"(A.y), "r"(A.z), "r"(A.w), "r"(b0), "r"(b1));
}

// ---------------------------------------------------------------------------
// Kernel 0: build A fragments, one uint4 per thread (unchanged layouts)
// ---------------------------------------------------------------------------
__global__ void prep_kernel(const float* __restrict__ w1,
                            const float* __restrict__ w2) {
    int idx = blockIdx.x * blockDim.x + threadIdx.x;
    int lane = idx & 31;
    int g = lane >> 2, tig = lane & 3;
    if (idx < 9216) {
        int F = idx >> 5;
        int split = F & 1, mt = (F >> 1) & 1, ks = (F >> 2) & 1;
        int ct = F >> 3;
        int tap = ct % 9, chunk = ct / 9;
        int ty = tap / 3, tx = tap % 3;
        uint wv[4];
#pragma unroll
        for (int r = 0; r < 4; r++) {
            int row = g + 8 * (r & 1), col = 2 * tig + 8 * (r >> 1);
            int m  = mt * 16 + row;
            int c0 = chunk * 32 + ks * 16 + col;
            float f0 = 0.f, f1 = 0.f;
            if (m < LK) {
                f0 = w1[((m * C_ + c0) * 3 + ty) * 3 + tx];
                f1 = w1[((m * C_ + c0 + 1) * 3 + ty) * 3 + tx];
            }
            uint hw, lw; split2(f0, f1, hw, lw);
            wv[r] = split ? lw : hw;
        }
        g_w1f[F * 32 + lane] = make_uint4(wv[0], wv[1], wv[2], wv[3]);
    }
    if (idx < 4096) {
        int F = idx >> 5;
        int split = F & 1, ks = (F >> 1) & 7, mt = F >> 4;
        uint wv[4];
#pragma unroll
        for (int r = 0; r < 4; r++) {
            int row = g + 8 * (r & 1), col = 2 * tig + 8 * (r >> 1);
            int o  = mt * 16 + row;
            int c0 = ks * 16 + col;
            float4 p0 = ((const float4*)w2)[o * 128 + c0];
            float4 p1 = ((const float4*)w2)[o * 128 + c0 + 1];
            float f0 = p0.x + p0.y + p0.z + p0.w;
            float f1 = p1.x + p1.y + p1.z + p1.w;
            uint hw, lw; split2(f0, f1, hw, lw);
            wv[r] = split ? lw : hw;
        }
        g_w2f[F * 32 + lane] = make_uint4(wv[0], wv[1], wv[2], wv[3]);
    }
}

// ---------------------------------------------------------------------------
// Fused kernel. 256 threads, 2 blocks/SM.
// Warp roles: pxG = wid&3 (16-px group = 2 pixel rows), mtH = wid>>2.
// smem (floats): xs 18432 (ysp4 2112 uint4 overlays) |
//                xsp4 1600 uint4 = 6400 w (red 2112 f overlays) | sk 1650
// ---------------------------------------------------------------------------
#define F_XS    (C_ * 144)
#define W_XSP   6400
#define F_SK    (25 * 66)
#define SM_TOT  ((F_XS + W_XSP + F_SK) * 4)

__global__ void __launch_bounds__(256, 2)
fused_kernel(const float* __restrict__ x, const float* __restrict__ b1,
             const float* __restrict__ b2, float* __restrict__ out) {
    extern __shared__ float sm[];
    float* xs   = sm;
    uint4* xsp4 = (uint4*)(sm + F_XS);
    float* red  = sm + F_XS;
    float* sk   = sm + F_XS + W_XSP;
    uint4* ysp4 = (uint4*)sm;

    int tid = threadIdx.x;
    int blk = blockIdx.x;
    int b   = blk >> 6;
    int t   = blk & 63;
    int h0  = (t >> 3) * 8;
    int w0  = (t & 7) * 8;
    const float* xb = x + b * C_ * H_ * W_;

    // ---- load x tile (halo 2, zero pad) ----
    for (int i = tid; i < C_ * 144; i += 256) {
        int c   = i / 144;
        int rem = i - c * 144;
        int yy  = rem / 12;
        int xx  = rem - yy * 12;
        int h = h0 - 2 + yy, w = w0 - 2 + xx;
        float v = 0.f;
        if ((unsigned)h < H_ && (unsigned)w < W_) v = xb[(c * H_ + h) * W_ + w];
        xs[i] = v;
    }

    int wid = tid >> 5, lane = tid & 31;
    int g = lane >> 2, tig = lane & 3;
    int pxG = wid & 3, mtH = wid >> 2;

    // ---- conv1: 2 chunks of 64 ch, packed-B mma, A reused over 2 B-tiles ----
    float dc[2][4];
#pragma unroll
    for (int bt = 0; bt < 2; bt++)
#pragma unroll
        for (int q = 0; q < 4; q++) dc[bt][q] = 0.f;

    for (int chunk = 0; chunk < 2; chunk++) {
        __syncthreads();
        // stage: xsp4[(ksl*100+pos)*4 + cpq] = {hi(cp), hi(cp+4), lo(cp), lo(cp+4)}
        // i mapping pos-fastest for conflict-free xs reads
        for (int i = tid; i < 1600; i += 256) {
            int pos = i % 100;
            int kc  = i / 100;            // ksl*4 + cpq
            int cpq = kc & 3, ksl = kc >> 2;
            int sy = pos / 10, sx = pos - sy * 10;
            int cb = chunk * 64 + (ksl * 8 + cpq) * 2;
            const float* xp = xs + (sy + 1) * 12 + sx + 1;
            float f0 = xp[cb * 144],        f1 = xp[(cb + 1) * 144];
            float f2 = xp[(cb + 8) * 144],  f3 = xp[(cb + 9) * 144];
            uint h0w, l0w, h1w, l1w;
            split2(f0, f1, h0w, l0w);
            split2(f2, f3, h1w, l1w);
            xsp4[(ksl * 100 + pos) * 4 + cpq] = make_uint4(h0w, h1w, l0w, l1w);
        }
        __syncthreads();

        for (int ksl = 0; ksl < 4; ksl++) {
            int c32  = chunk * 2 + (ksl >> 1);
            int ks16 = ksl & 1;
#pragma unroll
            for (int tap = 0; tap < 9; tap++) {
                int ty = tap / 3, tx = tap - ty * 3;
                int rowb = pxG * 2 + ty;
                uint4 q0 = xsp4[(ksl * 100 + rowb * 10 + g + tx) * 4 + tig];
                uint4 q1 = xsp4[(ksl * 100 + (rowb + 1) * 10 + g + tx) * 4 + tig];
                int F = (((c32 * 9 + tap) * 2 + ks16) * 2 + mtH) * 2;
                uint4 Ah = g_w1f[F * 32 + lane];
                uint4 Al = g_w1f[(F + 1) * 32 + lane];
                mma4(dc[0], Ah, q0.x, q0.y);
                mma4(dc[0], Ah, q0.z, q0.w);
                mma4(dc[0], Al, q0.x, q0.y);
                mma4(dc[1], Ah, q1.x, q1.y);
                mma4(dc[1], Ah, q1.z, q1.w);
                mma4(dc[1], Al, q1.x, q1.y);
            }
        }
    }

    __syncthreads();                    // xsp dead -> red overlay
    {
#pragma unroll
        for (int bt = 0; bt < 2; bt++) {
            int pxb = pxG * 16 + bt * 8 + 2 * tig;
            int m0  = mtH * 16 + g;
            red[pxb * 33 + m0]           = dc[bt][0];
            red[(pxb + 1) * 33 + m0]     = dc[bt][1];
            red[pxb * 33 + m0 + 8]       = dc[bt][2];
            red[(pxb + 1) * 33 + m0 + 8] = dc[bt][3];
        }
    }
    __syncthreads();

    // ---- softmax: one thread per pixel ----
    if (tid < 64) {
        int p = tid;
        float s[25];
        float m = -1e30f;
#pragma unroll
        for (int k = 0; k < 25; k++) {
            float v = red[p * 33 + k] + b1[k];
            s[k] = v;
            m = fmaxf(m, v);
        }
        float tot = 0.f;
#pragma unroll
        for (int k = 0; k < 25; k++) { s[k] = __expf(s[k] - m); tot += s[k]; }
        float inv = 1.f / tot;
#pragma unroll
        for (int k = 0; k < 25; k++) sk[k * 66 + p] = s[k] * inv;
    }
    __syncthreads();

    // ---- y phase: pixel pair per thread, 16 channels, float2 row loads ----
    int pp = tid & 31;                  // pixel pair id
    int cg = tid >> 5;                  // channel group (16 ch) == ks for ysp
    int px0 = 2 * pp;
    int pyy = px0 >> 3, pxx = px0 & 7;
    float ya[16], yb2[16];
    {
        float2 s2[25];
#pragma unroll
        for (int k = 0; k < 25; k++)
            s2[k] = *(const float2*)(sk + k * 66 + px0);
        const float* ub = xs + pyy * 12 + pxx;
#pragma unroll 2
        for (int j = 0; j < 16; j++) {
            int c = cg * 16 + j;
            const float* uc = ub + c * 144;
            float a0 = 0.f, a1 = 0.f;
#pragma unroll
            for (int ky = 0; ky < 5; ky++) {
                const float* ur = uc + ky * 12;
                float2 v0 = *(const float2*)(ur);
                float2 v1 = *(const float2*)(ur + 2);
                float2 v2 = *(const float2*)(ur + 4);
                float v[6] = {v0.x, v0.y, v1.x, v1.y, v2.x, v2.y};
#pragma unroll
                for (int kx = 0; kx < 5; kx++) {
                    a0 += s2[ky * 5 + kx].x * v[kx];
                    a1 += s2[ky * 5 + kx].y * v[kx + 1];
                }
            }
            ya[j] = a0; yb2[j] = a1;
        }
    }
    __syncthreads();                    // xs reads done -> ysp overlay

    // ---- pack y: ysp4[ks*264 + tig*66 + px] = {hi(cp),hi(cp+4),lo(cp),lo(cp+4)}
    {
#pragma unroll
        for (int tq = 0; tq < 4; tq++) {
            uint h0w, l0w, h1w, l1w;
            split2(ya[2 * tq], ya[2 * tq + 1], h0w, l0w);
            split2(ya[2 * tq + 8], ya[2 * tq + 9], h1w, l1w);
            ysp4[cg * 264 + tq * 66 + px0] = make_uint4(h0w, h1w, l0w, l1w);
            split2(yb2[2 * tq], yb2[2 * tq + 1], h0w, l0w);
            split2(yb2[2 * tq + 8], yb2[2 * tq + 9], h1w, l1w);
            ysp4[cg * 264 + tq * 66 + px0 + 1] = make_uint4(h0w, h1w, l0w, l1w);
        }
    }
    __syncthreads();

    // ---- z phase: z = w2eff * y, A reused over 2 B-tiles, 4 mt per warp ----
    float dz[2][4][4];
#pragma unroll
    for (int bt = 0; bt < 2; bt++)
#pragma unroll
        for (int mi = 0; mi < 4; mi++)
#pragma unroll
            for (int q = 0; q < 4; q++) dz[bt][mi][q] = 0.f;

#pragma unroll 2
    for (int ks = 0; ks < 8; ks++) {
        int pb = pxG * 16;
        uint4 q0 = ysp4[ks * 264 + tig * 66 + pb + g];
        uint4 q1 = ysp4[ks * 264 + tig * 66 + pb + 8 + g];
#pragma unroll
        for (int mi = 0; mi < 4; mi++) {
            int mt = mtH * 4 + mi;
            int F = (mt * 8 + ks) * 2;
            uint4 Ah = g_w2f[F * 32 + lane];
            uint4 Al = g_w2f[(F + 1) * 32 + lane];
            mma4(dz[0][mi], Ah, q0.x, q0.y);
            mma4(dz[0][mi], Ah, q0.z, q0.w);
            mma4(dz[0][mi], Al, q0.x, q0.y);
            mma4(dz[1][mi], Ah, q1.x, q1.y);
            mma4(dz[1][mi], Ah, q1.z, q1.w);
            mma4(dz[1][mi], Al, q1.x, q1.y);
        }
    }

    // ---- store with x2 nearest upsample ----
    {
        int cc0 = 2 * (w0 + 2 * tig);
#pragma unroll
        for (int bt = 0; bt < 2; bt++) {
            int hh = h0 + pxG * 2 + bt;          // source pixel row
#pragma unroll
            for (int mi = 0; mi < 4; mi++) {
#pragma unroll
                for (int half = 0; half < 2; half++) {
                    int o = (mtH * 4 + mi) * 16 + g + 8 * half;
                    float bo = b2[o];
                    float z0 = dz[bt][mi][2 * half]     + bo;
                    float z1 = dz[bt][mi][2 * half + 1] + bo;
                    float4 vv = make_float4(z0, z0, z1, z1);
                    size_t rowb = ((size_t)(b * OUT_ + o) * (2 * H_) + 2 * hh) * (2 * W_) + cc0;
                    *(float4*)(out + rowb)          = vv;
                    *(float4*)(out + rowb + 2 * W_) = vv;
                }
            }
        }
    }
}

// ---------------------------------------------------------------------------
extern "C" void kernel_launch(void* const* d_in, const int* in_sizes, int n_in,
                              void* d_out, int out_size) {
    const float* x  = (const float*)d_in[0];
    const float* w1 = (const float*)d_in[1];
    const float* b1 = (const float*)d_in[2];
    const float* w2 = (const float*)d_in[3];
    const float* b2 = (const float*)d_in[4];
    float* out = (float*)d_out;

    cudaFuncSetAttribute(fused_kernel,
                         cudaFuncAttributeMaxDynamicSharedMemorySize, SM_TOT);

    prep_kernel<<<36, 256>>>(w1, w2);
    fused_kernel<<<256, 256, SM_TOT>>>(x, b1, b2, out);
}

// round 9
// speedup vs baseline: 1.5651x; 1.5651x over previous
#include <cuda_runtime.h>
#include <cuda_bf16.h>
#include <math.h>

// Problem constants
#define B_   4
#define C_   128
#define H_   64
#define W_   64
#define OUT_ 128
#define LK   25

typedef unsigned int uint;

// ---------------------------------------------------------------------------
// Device scratch: bf16-split MMA A-fragments
// ---------------------------------------------------------------------------
__device__ uint4 g_w1f[288 * 32];   // conv: F=(((c32*9+tap)*2+ks16)*2+mt)*2+split
__device__ uint4 g_w2f[128 * 32];   // z:    F=(mt*8+ks)*2+split

__device__ __forceinline__ uint cvt2(float hi_src, float lo_src) {
    uint r;
    asm("cvt.rn.bf16x2.f32 %0, %1, %2;" : "=r"(r) : "f"(hi_src), "f"(lo_src));
    return r;
}
__device__ __forceinline__ float uaf(uint u) { return __uint_as_float(u); }

__device__ __forceinline__ void split2(float f0, float f1, uint& hw, uint& lw) {
    hw = cvt2(f1, f0);
    float h0 = uaf(hw << 16);
    float h1 = uaf(hw & 0xFFFF0000u);
    lw = cvt2(f1 - h1, f0 - h0);
}

__device__ __forceinline__ void mma4(float* d, uint4 A, uint b0, uint b1) {
    asm("mma.sync.aligned.m16n8k16.row.col.f32.bf16.bf16.f32 "
        "{%0,%1,%2,%3}, {%4,%5,%6,%7}, {%8,%9}, {%0,%1,%2,%3};"
        : "+f"(d[0]), "+f"(d[1]), "+f"(d[2]), "+f"(d[3])
        : "r"(A.x), "r"(A.y), "r"(A.z), "r"(A.w), "r"(b0), "r"(b1));
}

// ---------------------------------------------------------------------------
// Kernel 0: build A fragments, one uint4 per thread
// ---------------------------------------------------------------------------
__global__ void prep_kernel(const float* __restrict__ w1,
                            const float* __restrict__ w2) {
    int idx = blockIdx.x * blockDim.x + threadIdx.x;
    int lane = idx & 31;
    int g = lane >> 2, tig = lane & 3;
    if (idx < 9216) {
        int F = idx >> 5;
        int split = F & 1, mt = (F >> 1) & 1, ks = (F >> 2) & 1;
        int ct = F >> 3;
        int tap = ct % 9, chunk = ct / 9;
        int ty = tap / 3, tx = tap % 3;
        uint wv[4];
#pragma unroll
        for (int r = 0; r < 4; r++) {
            int row = g + 8 * (r & 1), col = 2 * tig + 8 * (r >> 1);
            int m  = mt * 16 + row;
            int c0 = chunk * 32 + ks * 16 + col;
            float f0 = 0.f, f1 = 0.f;
            if (m < LK) {
                f0 = w1[((m * C_ + c0) * 3 + ty) * 3 + tx];
                f1 = w1[((m * C_ + c0 + 1) * 3 + ty) * 3 + tx];
            }
            uint hw, lw; split2(f0, f1, hw, lw);
            wv[r] = split ? lw : hw;
        }
        g_w1f[F * 32 + lane] = make_uint4(wv[0], wv[1], wv[2], wv[3]);
    }
    if (idx < 4096) {
        int F = idx >> 5;
        int split = F & 1, ks = (F >> 1) & 7, mt = F >> 4;
        uint wv[4];
#pragma unroll
        for (int r = 0; r < 4; r++) {
            int row = g + 8 * (r & 1), col = 2 * tig + 8 * (r >> 1);
            int o  = mt * 16 + row;
            int c0 = ks * 16 + col;
            float4 p0 = ((const float4*)w2)[o * 128 + c0];
            float4 p1 = ((const float4*)w2)[o * 128 + c0 + 1];
            float f0 = p0.x + p0.y + p0.z + p0.w;
            float f1 = p1.x + p1.y + p1.z + p1.w;
            uint hw, lw; split2(f0, f1, hw, lw);
            wv[r] = split ? lw : hw;
        }
        g_w2f[F * 32 + lane] = make_uint4(wv[0], wv[1], wv[2], wv[3]);
    }
}

// ---------------------------------------------------------------------------
// Fused kernel. 256 threads, 2 blocks/SM.
// Warp roles: pxG = wid&3 (16-px group), mtH = wid>>2.
// ---------------------------------------------------------------------------
#define F_XS    (C_ * 144)
#define W_XSP   6400
#define F_SK    (25 * 66)
#define SM_TOT  ((F_XS + W_XSP + F_SK) * 4)

__global__ void __launch_bounds__(256, 2)
fused_kernel(const float* __restrict__ x, const float* __restrict__ b1,
             const float* __restrict__ b2, float* __restrict__ out) {
    extern __shared__ float sm[];
    float* xs   = sm;
    uint4* xsp4 = (uint4*)(sm + F_XS);
    float* red  = sm + F_XS;
    float* sk   = sm + F_XS + W_XSP;
    uint4* ysp4 = (uint4*)sm;

    int tid = threadIdx.x;
    int blk = blockIdx.x;
    int b   = blk >> 6;
    int t   = blk & 63;
    int h0  = (t >> 3) * 8;
    int w0  = (t & 7) * 8;
    const float* xb = x + b * C_ * H_ * W_;

    // ---- load x tile (halo 2, zero pad) ----
    for (int i = tid; i < C_ * 144; i += 256) {
        int c   = i / 144;
        int rem = i - c * 144;
        int yy  = rem / 12;
        int xx  = rem - yy * 12;
        int h = h0 - 2 + yy, w = w0 - 2 + xx;
        float v = 0.f;
        if ((unsigned)h < H_ && (unsigned)w < W_) v = xb[(c * H_ + h) * W_ + w];
        xs[i] = v;
    }

    int wid = tid >> 5, lane = tid & 31;
    int g = lane >> 2, tig = lane & 3;
    int pxG = wid & 3, mtH = wid >> 2;

    // ---- conv1: 2 chunks of 64 ch, packed-B mma, A reused over 2 B-tiles ----
    float dc[2][4];
#pragma unroll
    for (int bt = 0; bt < 2; bt++)
#pragma unroll
        for (int q = 0; q < 4; q++) dc[bt][q] = 0.f;

    for (int chunk = 0; chunk < 2; chunk++) {
        __syncthreads();
        // stage: xsp4[(ksl*100+pos)*4 + cpq] = {hi(cp), hi(cp+4), lo(cp), lo(cp+4)}
        for (int i = tid; i < 1600; i += 256) {
            int pos = i % 100;
            int kc  = i / 100;            // ksl*4 + cpq
            int cpq = kc & 3, ksl = kc >> 2;
            int sy = pos / 10, sx = pos - sy * 10;
            int cb = chunk * 64 + (ksl * 8 + cpq) * 2;
            const float* xp = xs + (sy + 1) * 12 + sx + 1;
            float f0 = xp[cb * 144],        f1 = xp[(cb + 1) * 144];
            float f2 = xp[(cb + 8) * 144],  f3 = xp[(cb + 9) * 144];
            uint h0w, l0w, h1w, l1w;
            split2(f0, f1, h0w, l0w);
            split2(f2, f3, h1w, l1w);
            xsp4[(ksl * 100 + pos) * 4 + cpq] = make_uint4(h0w, h1w, l0w, l1w);
        }
        __syncthreads();

        // FULLY UNROLLED: all fragment indices compile-time, LDGs batchable
#pragma unroll
        for (int ksl = 0; ksl < 4; ksl++) {
            int c32  = chunk * 2 + (ksl >> 1);
            int ks16 = ksl & 1;
#pragma unroll
            for (int tap = 0; tap < 9; tap++) {
                int ty = tap / 3, tx = tap - ty * 3;
                int rowb = pxG * 2 + ty;
                uint4 q0 = xsp4[(ksl * 100 + rowb * 10 + g + tx) * 4 + tig];
                uint4 q1 = xsp4[(ksl * 100 + (rowb + 1) * 10 + g + tx) * 4 + tig];
                int F = (((c32 * 9 + tap) * 2 + ks16) * 2 + mtH) * 2;
                uint4 Ah = g_w1f[F * 32 + lane];
                uint4 Al = g_w1f[(F + 1) * 32 + lane];
                mma4(dc[0], Ah, q0.x, q0.y);
                mma4(dc[0], Ah, q0.z, q0.w);
                mma4(dc[0], Al, q0.x, q0.y);
                mma4(dc[1], Ah, q1.x, q1.y);
                mma4(dc[1], Ah, q1.z, q1.w);
                mma4(dc[1], Al, q1.x, q1.y);
            }
        }
    }

    __syncthreads();                    // xsp dead -> red overlay
    {
#pragma unroll
        for (int bt = 0; bt < 2; bt++) {
            int pxb = pxG * 16 + bt * 8 + 2 * tig;
            int m0  = mtH * 16 + g;
            red[pxb * 33 + m0]           = dc[bt][0];
            red[(pxb + 1) * 33 + m0]     = dc[bt][1];
            red[pxb * 33 + m0 + 8]       = dc[bt][2];
            red[(pxb + 1) * 33 + m0 + 8] = dc[bt][3];
        }
    }
    __syncthreads();

    // ---- softmax: one thread per pixel ----
    if (tid < 64) {
        int p = tid;
        float s[25];
        float m = -1e30f;
#pragma unroll
        for (int k = 0; k < 25; k++) {
            float v = red[p * 33 + k] + b1[k];
            s[k] = v;
            m = fmaxf(m, v);
        }
        float tot = 0.f;
#pragma unroll
        for (int k = 0; k < 25; k++) { s[k] = __expf(s[k] - m); tot += s[k]; }
        float inv = 1.f / tot;
#pragma unroll
        for (int k = 0; k < 25; k++) sk[k * 66 + p] = s[k] * inv;
    }
    __syncthreads();

    // ---- y phase: pixel pair per thread, 16 channels, float2 row loads ----
    int pp = tid & 31;                  // pixel pair id
    int cg = tid >> 5;                  // channel group (16 ch) == ks for ysp
    int px0 = 2 * pp;
    int pyy = px0 >> 3, pxx = px0 & 7;
    float ya[16], yb2[16];
    {
        float2 s2[25];
#pragma unroll
        for (int k = 0; k < 25; k++)
            s2[k] = *(const float2*)(sk + k * 66 + px0);
        const float* ub = xs + pyy * 12 + pxx;
#pragma unroll 2
        for (int j = 0; j < 16; j++) {
            int c = cg * 16 + j;
            const float* uc = ub + c * 144;
            float a0 = 0.f, a1 = 0.f;
#pragma unroll
            for (int ky = 0; ky < 5; ky++) {
                const float* ur = uc + ky * 12;
                float2 v0 = *(const float2*)(ur);
                float2 v1 = *(const float2*)(ur + 2);
                float2 v2 = *(const float2*)(ur + 4);
                float v[6] = {v0.x, v0.y, v1.x, v1.y, v2.x, v2.y};
#pragma unroll
                for (int kx = 0; kx < 5; kx++) {
                    a0 += s2[ky * 5 + kx].x * v[kx];
                    a1 += s2[ky * 5 + kx].y * v[kx + 1];
                }
            }
            ya[j] = a0; yb2[j] = a1;
        }
    }
    __syncthreads();                    // xs reads done -> ysp overlay

    // ---- pack y: ysp4[ks*264 + tig*66 + px] = {hi(cp),hi(cp+4),lo(cp),lo(cp+4)}
    {
#pragma unroll
        for (int tq = 0; tq < 4; tq++) {
            uint h0w, l0w, h1w, l1w;
            split2(ya[2 * tq], ya[2 * tq + 1], h0w, l0w);
            split2(ya[2 * tq + 8], ya[2 * tq + 9], h1w, l1w);
            ysp4[cg * 264 + tq * 66 + px0] = make_uint4(h0w, h1w, l0w, l1w);
            split2(yb2[2 * tq], yb2[2 * tq + 1], h0w, l0w);
            split2(yb2[2 * tq + 8], yb2[2 * tq + 9], h1w, l1w);
            ysp4[cg * 264 + tq * 66 + px0 + 1] = make_uint4(h0w, h1w, l0w, l1w);
        }
    }
    __syncthreads();

    // ---- z phase: fully unrolled, A reused over 2 B-tiles, 4 mt per warp ----
    float dz[2][4][4];
#pragma unroll
    for (int bt = 0; bt < 2; bt++)
#pragma unroll
        for (int mi = 0; mi < 4; mi++)
#pragma unroll
            for (int q = 0; q < 4; q++) dz[bt][mi][q] = 0.f;

#pragma unroll
    for (int ks = 0; ks < 8; ks++) {
        int pb = pxG * 16;
        uint4 q0 = ysp4[ks * 264 + tig * 66 + pb + g];
        uint4 q1 = ysp4[ks * 264 + tig * 66 + pb + 8 + g];
#pragma unroll
        for (int mi = 0; mi < 4; mi++) {
            int mt = mtH * 4 + mi;
            int F = (mt * 8 + ks) * 2;
            uint4 Ah = g_w2f[F * 32 + lane];
            uint4 Al = g_w2f[(F + 1) * 32 + lane];
            mma4(dz[0][mi], Ah, q0.x, q0.y);
            mma4(dz[0][mi], Ah, q0.z, q0.w);
            mma4(dz[0][mi], Al, q0.x, q0.y);
            mma4(dz[1][mi], Ah, q1.x, q1.y);
            mma4(dz[1][mi], Ah, q1.z, q1.w);
            mma4(dz[1][mi], Al, q1.x, q1.y);
        }
    }

    // ---- store with x2 nearest upsample ----
    {
        int cc0 = 2 * (w0 + 2 * tig);
#pragma unroll
        for (int bt = 0; bt < 2; bt++) {
            int hh = h0 + pxG * 2 + bt;          // source pixel row
#pragma unroll
            for (int mi = 0; mi < 4; mi++) {
#pragma unroll
                for (int half = 0; half < 2; half++) {
                    int o = (mtH * 4 + mi) * 16 + g + 8 * half;
                    float bo = b2[o];
                    float z0 = dz[bt][mi][2 * half]     + bo;
                    float z1 = dz[bt][mi][2 * half + 1] + bo;
                    float4 vv = make_float4(z0, z0, z1, z1);
                    size_t rowb = ((size_t)(b * OUT_ + o) * (2 * H_) + 2 * hh) * (2 * W_) + cc0;
                    *(float4*)(out + rowb)          = vv;
                    *(float4*)(out + rowb + 2 * W_) = vv;
                }
            }
        }
    }
}

// ---------------------------------------------------------------------------
extern "C" void kernel_launch(void* const* d_in, const int* in_sizes, int n_in,
                              void* d_out, int out_size) {
    const float* x  = (const float*)d_in[0];
    const float* w1 = (const float*)d_in[1];
    const float* b1 = (const float*)d_in[2];
    const float* w2 = (const float*)d_in[3];
    const float* b2 = (const float*)d_in[4];
    float* out = (float*)d_out;

    cudaFuncSetAttribute(fused_kernel,
                         cudaFuncAttributeMaxDynamicSharedMemorySize, SM_TOT);

    prep_kernel<<<36, 256>>>(w1, w2);
    fused_kernel<<<256, 256, SM_TOT>>>(x, b1, b2, out);
}